// round 17
// baseline (speedup 1.0000x reference)
#include <cuda_runtime.h>
#include <cuda_fp16.h>
#include <cstdint>

// h (projected features) stored naturally [b][j][f] as fp16.
__device__ __align__(16) __half g_h_hi[4 * 2048 * 128];
__device__ float g_s[4 * 2048];

static __device__ __forceinline__ uint32_t smem_u32(const void* p) {
    uint32_t a;
    asm("{ .reg .u64 t; cvta.to.shared.u64 t, %1; cvt.u32.u64 %0, t; }" : "=r"(a) : "l"(p));
    return a;
}
static __device__ __forceinline__ void cp16(uint32_t dst, const void* src) {
    asm volatile("cp.async.cg.shared.global [%0], [%1], 16;" :: "r"(dst), "l"(src) : "memory");
}
static __device__ __forceinline__ void cp_commit() {
    asm volatile("cp.async.commit_group;" ::: "memory");
}
template <int N> static __device__ __forceinline__ void cp_waitg() {
    asm volatile("cp.async.wait_group %0;" :: "n"(N) : "memory");
}
static __device__ __forceinline__ void ldsm4(uint32_t* r, uint32_t a) {
    asm volatile("ldmatrix.sync.aligned.m8n8.x4.shared.b16 {%0,%1,%2,%3}, [%4];"
                 : "=r"(r[0]), "=r"(r[1]), "=r"(r[2]), "=r"(r[3]) : "r"(a));
}
static __device__ __forceinline__ void ldsm4t(uint32_t* r, uint32_t a) {
    asm volatile("ldmatrix.sync.aligned.m8n8.x4.trans.shared.b16 {%0,%1,%2,%3}, [%4];"
                 : "=r"(r[0]), "=r"(r[1]), "=r"(r[2]), "=r"(r[3]) : "r"(a));
}
static __device__ __forceinline__ void mma16816(float* c, const uint32_t* a,
                                                uint32_t b0, uint32_t b1) {
    asm volatile(
        "mma.sync.aligned.m16n8k16.row.col.f32.f16.f16.f32 "
        "{%0,%1,%2,%3}, {%4,%5,%6,%7}, {%8,%9}, {%0,%1,%2,%3};"
        : "+f"(c[0]), "+f"(c[1]), "+f"(c[2]), "+f"(c[3])
        : "r"(a[0]), "r"(a[1]), "r"(a[2]), "r"(a[3]), "r"(b0), "r"(b1));
}
static __device__ __forceinline__ float leaky(float x) {
    return fmaxf(x, 0.f) + 0.2f * fminf(x, 0.f);
}

// ---------------- K1: h = x@W via fp16 hi/lo 3-pass HMMA, s = h@a_w + ab ---
static constexpr int XP       = 272;
static constexpr int OFF_XHI  = 0;
static constexpr int OFF_XLO  = OFF_XHI + 64 * XP;
static constexpr int OFF_WHI  = OFF_XLO + 64 * XP;
static constexpr int OFF_WLO  = OFF_WHI + 128 * XP;
static constexpr int OFF_AW   = OFF_WLO + 128 * XP;
static constexpr int OFF_SSM  = OFF_AW + 512;
static constexpr int SM1_SIZE = OFF_SSM + 256;

__global__ void __launch_bounds__(256) k_prep(const float* __restrict__ x,
                                              const float* __restrict__ W,
                                              const float* __restrict__ aw,
                                              const float* __restrict__ ab) {
    extern __shared__ char smp[];
    const uint32_t sbp = smem_u32(smp);
    const int tid = threadIdx.x, wid = tid >> 5, lane = tid & 31;
    const int b = blockIdx.x >> 5;
    const int i0 = (blockIdx.x & 31) * 64;

    const float4* xb = (const float4*)(x + ((size_t)b * 2048 + i0) * 128);
#pragma unroll
    for (int k = 0; k < 8; k++) {
        int idx = tid + 256 * k;
        int row = idx >> 5, c4 = idx & 31;
        float4 v = xb[idx];
        __half2 h0 = __floats2half2_rn(v.x, v.y);
        __half2 h1 = __floats2half2_rn(v.z, v.w);
        float2 f0 = __half22float2(h0), f1 = __half22float2(h1);
        __half2 l0 = __floats2half2_rn(v.x - f0.x, v.y - f0.y);
        __half2 l1 = __floats2half2_rn(v.z - f1.x, v.w - f1.y);
        char* d = smp + OFF_XHI + row * XP + c4 * 8;
        *(uint2*)d = make_uint2(*(uint32_t*)&h0, *(uint32_t*)&h1);
        *(uint2*)(d + (OFF_XLO - OFF_XHI)) = make_uint2(*(uint32_t*)&l0, *(uint32_t*)&l1);
    }
    const float4* wb = (const float4*)W;
#pragma unroll
    for (int k = 0; k < 16; k++) {
        int idx = tid + 256 * k;
        int row = idx >> 5, c4 = idx & 31;
        float4 v = wb[idx];
        __half2 h0 = __floats2half2_rn(v.x, v.y);
        __half2 h1 = __floats2half2_rn(v.z, v.w);
        float2 f0 = __half22float2(h0), f1 = __half22float2(h1);
        __half2 l0 = __floats2half2_rn(v.x - f0.x, v.y - f0.y);
        __half2 l1 = __floats2half2_rn(v.z - f1.x, v.w - f1.y);
        char* d = smp + OFF_WHI + row * XP + c4 * 8;
        *(uint2*)d = make_uint2(*(uint32_t*)&h0, *(uint32_t*)&h1);
        *(uint2*)(d + (OFF_WLO - OFF_WHI)) = make_uint2(*(uint32_t*)&l0, *(uint32_t*)&l1);
    }
    if (tid < 128) ((float*)(smp + OFF_AW))[tid] = aw[tid];
    if (tid < 64) ((float*)(smp + OFF_SSM))[tid] = 0.f;
    __syncthreads();

    const int r0 = (wid & 3) * 16, c0 = (wid >> 2) * 64;
    float acc[8][4];
#pragma unroll
    for (int nb = 0; nb < 8; nb++)
#pragma unroll
        for (int q = 0; q < 4; q++) acc[nb][q] = 0.f;

    const uint32_t arow = (uint32_t)((r0 + (lane & 15)) * XP + ((lane >> 4) << 4));
    const uint32_t brow = (uint32_t)((lane & 15) * XP + ((lane >> 4) << 4) + c0 * 2);
#pragma unroll
    for (int kk = 0; kk < 8; kk++) {
        uint32_t aph[4], apl[4];
        ldsm4(aph, sbp + OFF_XHI + arow + kk * 32);
        ldsm4(apl, sbp + OFF_XLO + arow + kk * 32);
        const uint32_t hb = sbp + OFF_WHI + brow + kk * 16 * XP;
#pragma unroll
        for (int n0 = 0; n0 < 4; n0++) {
            uint32_t bh[4], bl[4];
            ldsm4t(bh, hb + n0 * 32);
            ldsm4t(bl, hb + (OFF_WLO - OFF_WHI) + n0 * 32);
            mma16816(acc[2 * n0],     aph, bh[0], bh[1]);
            mma16816(acc[2 * n0 + 1], aph, bh[2], bh[3]);
            mma16816(acc[2 * n0],     apl, bh[0], bh[1]);
            mma16816(acc[2 * n0 + 1], apl, bh[2], bh[3]);
            mma16816(acc[2 * n0],     aph, bl[0], bl[1]);
            mma16816(acc[2 * n0 + 1], aph, bl[2], bl[3]);
        }
    }

    const float* awp = (const float*)(smp + OFF_AW);
    float* ssm = (float*)(smp + OFF_SSM);
    const int row_lo = r0 + (lane >> 2);
    __half* hout0 = g_h_hi + ((size_t)b * 2048 + i0 + row_lo) * 128;
    __half* hout1 = hout0 + 8 * 128;
    float s0 = 0.f, s1 = 0.f;
#pragma unroll
    for (int nb = 0; nb < 8; nb++) {
        const int col = c0 + nb * 8 + (lane & 3) * 2;
        __half2 o0 = __floats2half2_rn(acc[nb][0], acc[nb][1]);
        __half2 o1 = __floats2half2_rn(acc[nb][2], acc[nb][3]);
        *(uint32_t*)(hout0 + col) = *(uint32_t*)&o0;
        *(uint32_t*)(hout1 + col) = *(uint32_t*)&o1;
        s0 += acc[nb][0] * awp[col] + acc[nb][1] * awp[col + 1];
        s1 += acc[nb][2] * awp[col] + acc[nb][3] * awp[col + 1];
    }
    s0 += __shfl_xor_sync(0xffffffffu, s0, 1);
    s0 += __shfl_xor_sync(0xffffffffu, s0, 2);
    s1 += __shfl_xor_sync(0xffffffffu, s1, 1);
    s1 += __shfl_xor_sync(0xffffffffu, s1, 2);
    if ((lane & 3) == 0) {
        atomicAdd(&ssm[row_lo], s0);
        atomicAdd(&ssm[row_lo + 8], s1);
    }
    __syncthreads();
    if (tid < 64) g_s[b * 2048 + i0 + tid] = ssm[tid] + ab[0];
}

// ---------------- K2: HOMOGENEOUS warps: every warp produces AND consumes --
// 512 threads, 16 warps. Per interval t: produce P(t+1) (exp->STS),
// prefetch H(t+2) (cp.async), consume chunk t (LDSM+MMA). 1 barrier/chunk.
// Consumer tiling: warp w -> rows (w&3)*16, cols (w>>2)*32 (4x4 groups).
// P production: thread -> row tid>>3, cols (tid&7)*8..+8 (one uint4 STS).
// P: 2 stages. H: 4 stages (prefetch distance 2).
static constexpr int P_PITCH = 144;
static constexpr int H_PITCH = 272;
static constexpr int P_ST    = 64 * P_PITCH;        // 9216
static constexpr int H_ST    = 64 * H_PITCH;        // 17408
static constexpr int OFF_P   = 0;                   // 2 stages -> 18432
static constexpr int OFF_H   = 2 * P_ST;            // 18432; 4 stages -> 69632
static constexpr int OFF_SS   = OFF_H + 4 * H_ST;   // 88064 (2048 f)
static constexpr int OFF_BIAS = OFF_SS + 8192;      // 96256 (128 f)
static constexpr int OFF_LS   = OFF_BIAS + 512;     // 96768 (64 f)
static constexpr int OFF_SMAX = OFF_LS + 256;       // 97024 (1 f)
static constexpr int SM2_SIZE = OFF_SMAX + 16;      // 97040

__global__ void __launch_bounds__(512) k_attn(const float* __restrict__ A,
                                              const float* __restrict__ bias,
                                              float* __restrict__ out) {
    extern __shared__ char sm[];
    const uint32_t sb = smem_u32(sm);
    const int tid = threadIdx.x, wid = tid >> 5, lane = tid & 31;
    const int b = blockIdx.x >> 5;
    const int i0 = (blockIdx.x & 31) << 6;

    const __half* Hhig = g_h_hi + (size_t)b * 2048 * 128;

    // ---- H cp.async mapping: 1024 granules (16B), 2 per thread ----
    // granule g: row g>>4, col-chunk g&15
    // issue H(0), H(1) immediately
#pragma unroll
    for (int tc = 0; tc < 2; tc++) {
        const uint32_t bb = sb + OFF_H + tc * H_ST;
#pragma unroll
        for (int c = 0; c < 2; c++) {
            const int g = tid + 512 * c;
            const int jr = g >> 4, fc = g & 15;
            cp16(bb + jr * H_PITCH + fc * 16,
                 Hhig + (size_t)(tc * 64 + jr) * 128 + fc * 8);
        }
        cp_commit();
    }

    float* ss = (float*)(sm + OFF_SS);
    {   // preload s for whole batch + bias
        const float4* sg = (const float4*)(g_s + b * 2048);
        ((float4*)ss)[tid] = sg[tid];
        if (tid < 128) ((float*)(sm + OFF_BIAS))[tid] = bias[tid];
    }
    __syncthreads();

    // batch-wide max of s (fp16-safe shift)
    {
        float mx = -1e30f;
#pragma unroll
        for (int k = 0; k < 4; k++) mx = fmaxf(mx, ss[tid + 512 * k]);
#pragma unroll
        for (int off = 16; off >= 1; off >>= 1)
            mx = fmaxf(mx, __shfl_xor_sync(0xffffffffu, mx, off));
        if (lane == 0) ((float*)(sm + OFF_LS))[wid] = mx;
    }
    __syncthreads();
    if (tid == 0) {
        float mx = -1e30f;
#pragma unroll
        for (int w = 0; w < 16; w++) mx = fmaxf(mx, ((float*)(sm + OFF_LS))[w]);
        *(float*)(sm + OFF_SMAX) = mx;
    }
    __syncthreads();
    const float smax = *(const float*)(sm + OFF_SMAX);

    // ---- produce-side state (every thread) ----
    const int prow = tid >> 3;           // P row 0..63
    const int pc   = (tid & 7) * 8;      // 8 j-columns
    const float s_i = ss[i0 + prow];
    const float m_i = leaky(s_i + smax);
    float lsum = 0.f;
    const float* Arow = A + ((size_t)b * 2048 + i0 + prow) * 2048;

    // ---- consume-side state (every warp) ----
    const int r0 = (wid & 3) * 16, c0 = (wid >> 2) * 32;
    float acc[4][4];
#pragma unroll
    for (int nb = 0; nb < 4; nb++)
#pragma unroll
        for (int q = 0; q < 4; q++) acc[nb][q] = 0.f;
    const uint32_t arow = (uint32_t)((r0 + (lane & 15)) * P_PITCH + ((lane >> 4) << 4));
    const uint32_t brow = (uint32_t)((lane & 15) * H_PITCH + ((lane >> 4) << 4) + c0 * 2);

    // produce P(0) (A(0) loaded directly)
    {
        float4 a0 = *(const float4*)(Arow + pc);
        float4 a1 = *(const float4*)(Arow + pc + 4);
        float4 sv0 = *(const float4*)(ss + pc);
        float4 sv1 = *(const float4*)(ss + pc + 4);
        float pv[8];
        pv[0] = __expf(leaky(s_i + sv0.x) - m_i + a0.x);
        pv[1] = __expf(leaky(s_i + sv0.y) - m_i + a0.y);
        pv[2] = __expf(leaky(s_i + sv0.z) - m_i + a0.z);
        pv[3] = __expf(leaky(s_i + sv0.w) - m_i + a0.w);
        pv[4] = __expf(leaky(s_i + sv1.x) - m_i + a1.x);
        pv[5] = __expf(leaky(s_i + sv1.y) - m_i + a1.y);
        pv[6] = __expf(leaky(s_i + sv1.z) - m_i + a1.z);
        pv[7] = __expf(leaky(s_i + sv1.w) - m_i + a1.w);
#pragma unroll
        for (int q = 0; q < 8; q++) lsum += pv[q];
        __half2 h[4];
#pragma unroll
        for (int q = 0; q < 4; q++) h[q] = __floats2half2_rn(pv[2 * q], pv[2 * q + 1]);
        *(uint4*)(sm + OFF_P + prow * P_PITCH + pc * 2) = *(uint4*)h;
    }
    // A prefetch for chunk 1
    float4 av0 = *(const float4*)(Arow + 64 + pc);
    float4 av1 = *(const float4*)(Arow + 64 + pc + 4);

    cp_waitg<1>();   // H(0) complete (H(1) may be pending)
    __syncthreads(); // P(0) visible

#pragma unroll 1
    for (int t = 0; t < 32; t++) {
        // ---- prefetch H(t+2) ----
        if (t < 30) {
            const uint32_t bbn = sb + OFF_H + ((t + 2) & 3) * H_ST;
#pragma unroll
            for (int c = 0; c < 2; c++) {
                const int g = tid + 512 * c;
                const int jr = g >> 4, fc = g & 15;
                cp16(bbn + jr * H_PITCH + fc * 16,
                     Hhig + (size_t)((t + 2) * 64 + jr) * 128 + fc * 8);
            }
            cp_commit();
        }

        // ---- produce P(t+1) ----
        if (t < 31) {
            const int j1 = (t + 1) * 64;
            float4 sv0 = *(const float4*)(ss + j1 + pc);
            float4 sv1 = *(const float4*)(ss + j1 + pc + 4);
            float pv[8];
            pv[0] = __expf(leaky(s_i + sv0.x) - m_i + av0.x);
            pv[1] = __expf(leaky(s_i + sv0.y) - m_i + av0.y);
            pv[2] = __expf(leaky(s_i + sv0.z) - m_i + av0.z);
            pv[3] = __expf(leaky(s_i + sv0.w) - m_i + av0.w);
            pv[4] = __expf(leaky(s_i + sv1.x) - m_i + av1.x);
            pv[5] = __expf(leaky(s_i + sv1.y) - m_i + av1.y);
            pv[6] = __expf(leaky(s_i + sv1.z) - m_i + av1.z);
            pv[7] = __expf(leaky(s_i + sv1.w) - m_i + av1.w);
#pragma unroll
            for (int q = 0; q < 8; q++) lsum += pv[q];
            __half2 h[4];
#pragma unroll
            for (int q = 0; q < 4; q++) h[q] = __floats2half2_rn(pv[2 * q], pv[2 * q + 1]);
            *(uint4*)(sm + OFF_P + ((t + 1) & 1) * P_ST + prow * P_PITCH + pc * 2) = *(uint4*)h;

            // A prefetch chunk t+2
            if (t < 30) {
                av0 = *(const float4*)(Arow + (t + 2) * 64 + pc);
                av1 = *(const float4*)(Arow + (t + 2) * 64 + pc + 4);
            }
        }

        // ---- consume chunk t ----
        {
            const uint32_t pb = sb + OFF_P + (t & 1) * P_ST;
            const uint32_t hb0 = sb + OFF_H + (t & 3) * H_ST;
#pragma unroll
            for (int kk = 0; kk < 4; kk++) {
                uint32_t ap[4];
                ldsm4(ap, pb + arow + kk * 32);
                const uint32_t hb = hb0 + brow + kk * 16 * H_PITCH;
                uint32_t bh0[4], bh1[4];
                ldsm4t(bh0, hb);
                ldsm4t(bh1, hb + 32);
                mma16816(acc[0], ap, bh0[0], bh0[1]);
                mma16816(acc[1], ap, bh0[2], bh0[3]);
                mma16816(acc[2], ap, bh1[0], bh1[1]);
                mma16816(acc[3], ap, bh1[2], bh1[3]);
            }
        }

        // H(t+1) must be complete before next interval's consume
        if (t < 30)       cp_waitg<1>();
        else if (t == 30) cp_waitg<0>();
        __syncthreads();
    }

    // ---- lsum reduction: 8 threads per row ----
    {
        float v = lsum;
        v += __shfl_xor_sync(0xffffffffu, v, 1);
        v += __shfl_xor_sync(0xffffffffu, v, 2);
        v += __shfl_xor_sync(0xffffffffu, v, 4);
        if ((lane & 7) == 0) ((float*)(sm + OFF_LS))[tid >> 3] = v;
    }
    __syncthreads();

    // ---- epilogue ----
    {
        const float* ls = (const float*)(sm + OFF_LS);
        const float* bs = (const float*)(sm + OFF_BIAS);
        const int row_lo = r0 + (lane >> 2);
        const float linv0 = 1.0f / ls[row_lo];
        const float linv1 = 1.0f / ls[row_lo + 8];
        float* orow0 = out + ((size_t)b * 2048 + i0 + row_lo) * 128;
        float* orow1 = orow0 + 8 * 128;
#pragma unroll
        for (int nb = 0; nb < 4; nb++) {
            const int col = c0 + nb * 8 + (lane & 3) * 2;
            float2 o0 = make_float2(acc[nb][0] * linv0 + bs[col],
                                    acc[nb][1] * linv0 + bs[col + 1]);
            float2 o1 = make_float2(acc[nb][2] * linv1 + bs[col],
                                    acc[nb][3] * linv1 + bs[col + 1]);
            *(float2*)(orow0 + col) = o0;
            *(float2*)(orow1 + col) = o1;
        }
    }
}

extern "C" void kernel_launch(void* const* d_in, const int* in_sizes, int n_in,
                              void* d_out, int out_size) {
    (void)in_sizes; (void)n_in; (void)out_size;
    const float* x    = (const float*)d_in[0];
    const float* A    = (const float*)d_in[1];
    const float* W    = (const float*)d_in[2];
    const float* aw   = (const float*)d_in[3];
    const float* ab   = (const float*)d_in[4];
    const float* bias = (const float*)d_in[5];
    float* out = (float*)d_out;

    cudaFuncSetAttribute(k_prep, cudaFuncAttributeMaxDynamicSharedMemorySize, SM1_SIZE);
    cudaFuncSetAttribute(k_attn, cudaFuncAttributeMaxDynamicSharedMemorySize, SM2_SIZE);

    k_prep<<<128, 256, SM1_SIZE>>>(x, W, aw, ab);
    k_attn<<<128, 512, SM2_SIZE>>>(A, bias, out);
}